// round 1
// baseline (speedup 1.0000x reference)
#include <cuda_runtime.h>
#include <cuda_bf16.h>
#include <cstdint>

// Problem constants (fixed by the dataset)
#define NN 100000
#define EE 1600000
#define D  128          // feature dim (in and out)
#define KTOT 384        // D*(K+1)

typedef unsigned long long ull;

// ---------------- scratch (static device globals; no allocation) -------------
__device__ float g_f1[(size_t)NN * D];     // hop-1 features
__device__ float g_f2[(size_t)NN * D];     // hop-2 features
__device__ int   g_deg[NN];
__device__ int   g_cursor[NN];
__device__ int   g_rowptr[NN + 1];
__device__ int   g_dst[EE];
__device__ float g_val[EE];

// ---------------- packed fp32x2 helpers (Blackwell FFMA2 path) ---------------
__device__ __forceinline__ ull pack2(float x, float y) {
    ull r;
    asm("mov.b64 %0, {%1, %2};" : "=l"(r) : "f"(x), "f"(y));
    return r;
}
__device__ __forceinline__ void unpack2(ull v, float& lo, float& hi) {
    asm("mov.b64 {%0, %1}, %2;" : "=f"(lo), "=f"(hi) : "l"(v));
}
__device__ __forceinline__ void fma2(ull& d, ull a, ull b) {
    asm("fma.rn.f32x2 %0, %1, %2, %3;" : "=l"(d) : "l"(a), "l"(b), "l"(d));
}

// ---------------- CSR build ---------------------------------------------------
__global__ void zero_deg_kernel() {
    int i = blockIdx.x * blockDim.x + threadIdx.x;
    if (i < NN) g_deg[i] = 0;
}

__global__ void hist_kernel(const int* __restrict__ src) {
    int e = blockIdx.x * blockDim.x + threadIdx.x;
    if (e < EE) atomicAdd(&g_deg[src[e]], 1);
}

// Single-block exclusive scan over g_deg -> g_rowptr (+ g_cursor copy).
__global__ void scan_kernel() {
    __shared__ int warpsums[32];
    __shared__ int s_carry;
    int tid = threadIdx.x, lane = tid & 31, wid = tid >> 5;
    if (tid == 0) s_carry = 0;
    __syncthreads();

    for (int base = 0; base < NN; base += 1024) {
        int i = base + tid;
        int v = (i < NN) ? g_deg[i] : 0;
        int val = v;
        #pragma unroll
        for (int off = 1; off < 32; off <<= 1) {
            int t = __shfl_up_sync(0xffffffffu, val, off);
            if (lane >= off) val += t;
        }
        if (lane == 31) warpsums[wid] = val;
        __syncthreads();
        if (wid == 0) {
            int w = warpsums[lane];
            #pragma unroll
            for (int off = 1; off < 32; off <<= 1) {
                int t = __shfl_up_sync(0xffffffffu, w, off);
                if (lane >= off) w += t;
            }
            warpsums[lane] = w;
        }
        __syncthreads();
        int carry = s_carry;
        int incl  = val + (wid > 0 ? warpsums[wid - 1] : 0);
        int excl  = incl - v + carry;
        if (i < NN) { g_rowptr[i] = excl; g_cursor[i] = excl; }
        int total = warpsums[31];
        __syncthreads();
        if (tid == 0) s_carry = carry + total;
        __syncthreads();
    }
    if (threadIdx.x == 0) g_rowptr[NN] = s_carry;  // == EE
}

__global__ void scatter_kernel(const int* __restrict__ src,
                               const int* __restrict__ dst,
                               const float* __restrict__ val) {
    int e = blockIdx.x * blockDim.x + threadIdx.x;
    if (e < EE) {
        int pos = atomicAdd(&g_cursor[src[e]], 1);
        g_dst[pos] = dst[e];
        g_val[pos] = val[e];
    }
}

// ---------------- SpMM: one warp per row, gather + register accumulate -------
__global__ __launch_bounds__(256)
void spmm_kernel(const float4* __restrict__ fin, float4* __restrict__ fout) {
    int warp = (blockIdx.x * blockDim.x + threadIdx.x) >> 5;
    int lane = threadIdx.x & 31;
    if (warp >= NN) return;
    int beg = __ldg(&g_rowptr[warp]);
    int end = __ldg(&g_rowptr[warp + 1]);

    float4 acc = make_float4(0.f, 0.f, 0.f, 0.f);
    int j = beg;
    for (; j + 4 <= end; j += 4) {
        int   d0 = __ldg(&g_dst[j]),     d1 = __ldg(&g_dst[j + 1]);
        int   d2 = __ldg(&g_dst[j + 2]), d3 = __ldg(&g_dst[j + 3]);
        float v0 = __ldg(&g_val[j]),     v1 = __ldg(&g_val[j + 1]);
        float v2 = __ldg(&g_val[j + 2]), v3 = __ldg(&g_val[j + 3]);
        float4 a0 = fin[(size_t)d0 * 32 + lane];
        float4 a1 = fin[(size_t)d1 * 32 + lane];
        float4 a2 = fin[(size_t)d2 * 32 + lane];
        float4 a3 = fin[(size_t)d3 * 32 + lane];
        acc.x = fmaf(v0, a0.x, fmaf(v1, a1.x, fmaf(v2, a2.x, fmaf(v3, a3.x, acc.x))));
        acc.y = fmaf(v0, a0.y, fmaf(v1, a1.y, fmaf(v2, a2.y, fmaf(v3, a3.y, acc.y))));
        acc.z = fmaf(v0, a0.z, fmaf(v1, a1.z, fmaf(v2, a2.z, fmaf(v3, a3.z, acc.z))));
        acc.w = fmaf(v0, a0.w, fmaf(v1, a1.w, fmaf(v2, a2.w, fmaf(v3, a3.w, acc.w))));
    }
    for (; j < end; j++) {
        int   d = __ldg(&g_dst[j]);
        float v = __ldg(&g_val[j]);
        float4 a = fin[(size_t)d * 32 + lane];
        acc.x = fmaf(v, a.x, acc.x);
        acc.y = fmaf(v, a.y, acc.y);
        acc.z = fmaf(v, a.z, acc.z);
        acc.w = fmaf(v, a.w, acc.w);
    }
    fout[(size_t)warp * 32 + lane] = acc;
}

// ---------------- Dense: out = [x | f1 | f2] @ W^T + b  (fp32x2 packed FMA) --
// Block tile 128x128, 256 threads, 8x8 thread tile, BK = 16.
__global__ __launch_bounds__(256)
void gemm_kernel(const float* __restrict__ x,
                 const float* __restrict__ W,     // [128, 384] row-major
                 const float* __restrict__ bias,  // [128]
                 float* __restrict__ out) {
    __shared__ __align__(16) float As[16][128];
    __shared__ __align__(16) float Bs[16][128];

    int tid = threadIdx.x;
    int tx = tid & 15;        // col group (8 cols each)
    int ty = tid >> 4;        // row group (8 rows each)
    int rbase = blockIdx.x * 128;

    ull acc[8][4];
    #pragma unroll
    for (int r = 0; r < 8; r++)
        #pragma unroll
        for (int c = 0; c < 4; c++) acc[r][c] = pack2(0.f, 0.f);

    for (int kc = 0; kc < KTOT; kc += 16) {
        const float* src = (kc < 128) ? x : (kc < 256) ? g_f1 : g_f2;
        int ck = kc & 127;

        // Load A tile (128 rows x 16 cols), transposed into As[k][m]
        #pragma unroll
        for (int p = 0; p < 2; p++) {
            int idx = tid + p * 256;
            int row = idx >> 2, c4 = idx & 3;
            int grow = rbase + row;
            float4 v = make_float4(0.f, 0.f, 0.f, 0.f);
            if (grow < NN)
                v = ((const float4*)src)[(size_t)grow * 32 + (ck >> 2) + c4];
            As[c4 * 4 + 0][row] = v.x;
            As[c4 * 4 + 1][row] = v.y;
            As[c4 * 4 + 2][row] = v.z;
            As[c4 * 4 + 3][row] = v.w;
        }
        // Load B tile: W[o][kc..kc+15] into Bs[k][o]
        #pragma unroll
        for (int p = 0; p < 2; p++) {
            int idx = tid + p * 256;
            int o = idx >> 2, c4 = idx & 3;
            float4 v = ((const float4*)W)[(size_t)o * 96 + (kc >> 2) + c4];
            Bs[c4 * 4 + 0][o] = v.x;
            Bs[c4 * 4 + 1][o] = v.y;
            Bs[c4 * 4 + 2][o] = v.z;
            Bs[c4 * 4 + 3][o] = v.w;
        }
        __syncthreads();

        #pragma unroll
        for (int kk = 0; kk < 16; kk++) {
            float a[8];
            *(float4*)&a[0] = *(const float4*)&As[kk][ty * 8];
            *(float4*)&a[4] = *(const float4*)&As[kk][ty * 8 + 4];
            ull b2[4];
            #pragma unroll
            for (int c = 0; c < 4; c++)
                b2[c] = *(const ull*)&Bs[kk][tx * 8 + c * 2];
            #pragma unroll
            for (int r = 0; r < 8; r++) {
                ull a2 = pack2(a[r], a[r]);
                #pragma unroll
                for (int c = 0; c < 4; c++) fma2(acc[r][c], a2, b2[c]);
            }
        }
        __syncthreads();
    }

    // Epilogue: unpack, add bias, store
    float bb[8];
    #pragma unroll
    for (int c = 0; c < 8; c++) bb[c] = __ldg(&bias[tx * 8 + c]);

    #pragma unroll
    for (int r = 0; r < 8; r++) {
        int grow = rbase + ty * 8 + r;
        if (grow < NN) {
            float o8[8];
            #pragma unroll
            for (int c = 0; c < 4; c++) unpack2(acc[r][c], o8[2 * c], o8[2 * c + 1]);
            #pragma unroll
            for (int c = 0; c < 8; c++) o8[c] += bb[c];
            float4* po = (float4*)&out[(size_t)grow * 128 + tx * 8];
            po[0] = make_float4(o8[0], o8[1], o8[2], o8[3]);
            po[1] = make_float4(o8[4], o8[5], o8[6], o8[7]);
        }
    }
}

// ---------------- launch ------------------------------------------------------
extern "C" void kernel_launch(void* const* d_in, const int* in_sizes, int n_in,
                              void* d_out, int out_size) {
    const float* x        = (const float*)d_in[0];
    const int*   edge_src = (const int*)  d_in[1];
    const int*   edge_dst = (const int*)  d_in[2];
    const float* edge_val = (const float*)d_in[3];
    const float* W        = (const float*)d_in[4];
    const float* b        = (const float*)d_in[5];
    float* out = (float*)d_out;

    float *f1p, *f2p;
    cudaGetSymbolAddress((void**)&f1p, g_f1);
    cudaGetSymbolAddress((void**)&f2p, g_f2);

    // 1) CSR build (keyed by edge_src)
    zero_deg_kernel<<<(NN + 255) / 256, 256>>>();
    hist_kernel<<<(EE + 255) / 256, 256>>>(edge_src);
    scan_kernel<<<1, 1024>>>();
    scatter_kernel<<<(EE + 255) / 256, 256>>>(edge_src, edge_dst, edge_val);

    // 2) Two SpMM hops
    int spmm_blocks = (NN + 7) / 8;  // 8 warps (rows) per 256-thread block
    spmm_kernel<<<spmm_blocks, 256>>>((const float4*)x,  (float4*)f1p);
    spmm_kernel<<<spmm_blocks, 256>>>((const float4*)f1p, (float4*)f2p);

    // 3) Dense layer on [x | f1 | f2]
    gemm_kernel<<<(NN + 127) / 128, 256>>>(x, W, b, out);
}

// round 3
// speedup vs baseline: 1.5244x; 1.5244x over previous
#include <cuda_runtime.h>
#include <cuda_bf16.h>
#include <cstdint>

// Problem constants (fixed by the dataset)
#define NN 100000
#define EE 1600000
#define D  128
#define KTOT 384

typedef unsigned long long ull;

// ---------------- scratch (static device globals; no allocation) -------------
__device__ float g_f1[(size_t)NN * D];
__device__ float g_f2[(size_t)NN * D];
__device__ int   g_deg[NN];
__device__ int   g_cursor[NN];
__device__ int   g_rowptr[NN + 1];
__device__ int   g_dst[EE];
__device__ float g_val[EE];
// Pre-swizzled bf16 hi/lo images of W: 6 K-chunks of [128 n][64 k] bf16 (16 KB each)
__device__ __align__(16) unsigned char g_Wh[6 * 16384];
__device__ __align__(16) unsigned char g_Wl[6 * 16384];

// ---------------- PTX helpers -------------------------------------------------
__device__ __forceinline__ uint32_t smem_u32(const void* p) {
    uint32_t a;
    asm("{ .reg .u64 t; cvta.to.shared.u64 t, %1; cvt.u32.u64 %0, t; }" : "=r"(a) : "l"(p));
    return a;
}

#define LDSM4(R, A)                                                         \
    asm volatile("ldmatrix.sync.aligned.m8n8.x4.shared.b16 "                \
                 "{%0,%1,%2,%3}, [%4];"                                     \
                 : "=r"((R)[0]), "=r"((R)[1]), "=r"((R)[2]), "=r"((R)[3])   \
                 : "r"(A))

#define MMA16816(DD, AA, B0, B1)                                            \
    asm volatile("mma.sync.aligned.m16n8k16.row.col.f32.bf16.bf16.f32 "     \
                 "{%0,%1,%2,%3},{%4,%5,%6,%7},{%8,%9},{%0,%1,%2,%3};"       \
                 : "+f"((DD)[0]), "+f"((DD)[1]), "+f"((DD)[2]), "+f"((DD)[3]) \
                 : "r"((AA)[0]), "r"((AA)[1]), "r"((AA)[2]), "r"((AA)[3]),  \
                   "r"(B0), "r"(B1))

__device__ __forceinline__ uint32_t swz(uint32_t bo) {
    return bo ^ ((bo >> 3) & 0x70);
}

// ---------------- CSR build ---------------------------------------------------
__global__ void zero_deg_kernel() {
    int i = blockIdx.x * blockDim.x + threadIdx.x;
    if (i < NN) g_deg[i] = 0;
}

__global__ void hist_kernel(const int* __restrict__ src) {
    int e = blockIdx.x * blockDim.x + threadIdx.x;
    if (e < EE) atomicAdd(&g_deg[src[e]], 1);
}

__global__ void scan_kernel() {
    __shared__ int warpsums[32];
    __shared__ int s_carry;
    int tid = threadIdx.x, lane = tid & 31, wid = tid >> 5;
    if (tid == 0) s_carry = 0;
    __syncthreads();

    for (int base = 0; base < NN; base += 1024) {
        int i = base + tid;
        int v = (i < NN) ? g_deg[i] : 0;
        int val = v;
        #pragma unroll
        for (int off = 1; off < 32; off <<= 1) {
            int t = __shfl_up_sync(0xffffffffu, val, off);
            if (lane >= off) val += t;
        }
        if (lane == 31) warpsums[wid] = val;
        __syncthreads();
        if (wid == 0) {
            int w = warpsums[lane];
            #pragma unroll
            for (int off = 1; off < 32; off <<= 1) {
                int t = __shfl_up_sync(0xffffffffu, w, off);
                if (lane >= off) w += t;
            }
            warpsums[lane] = w;
        }
        __syncthreads();
        int carry = s_carry;
        int incl  = val + (wid > 0 ? warpsums[wid - 1] : 0);
        int excl  = incl - v + carry;
        if (i < NN) { g_rowptr[i] = excl; g_cursor[i] = excl; }
        int total = warpsums[31];
        __syncthreads();
        if (tid == 0) s_carry = carry + total;
        __syncthreads();
    }
    if (threadIdx.x == 0) g_rowptr[NN] = s_carry;
}

__global__ void scatter_kernel(const int* __restrict__ src,
                               const int* __restrict__ dst,
                               const float* __restrict__ val) {
    int e = blockIdx.x * blockDim.x + threadIdx.x;
    if (e < EE) {
        int pos = atomicAdd(&g_cursor[src[e]], 1);
        g_dst[pos] = dst[e];
        g_val[pos] = val[e];
    }
}

// ---------------- SpMM: one warp per row -------------------------------------
__global__ __launch_bounds__(256)
void spmm_kernel(const float4* __restrict__ fin, float4* __restrict__ fout) {
    int warp = (blockIdx.x * blockDim.x + threadIdx.x) >> 5;
    int lane = threadIdx.x & 31;
    if (warp >= NN) return;
    int beg = __ldg(&g_rowptr[warp]);
    int end = __ldg(&g_rowptr[warp + 1]);

    float4 acc = make_float4(0.f, 0.f, 0.f, 0.f);
    int j = beg;
    for (; j + 4 <= end; j += 4) {
        int   d0 = __ldg(&g_dst[j]),     d1 = __ldg(&g_dst[j + 1]);
        int   d2 = __ldg(&g_dst[j + 2]), d3 = __ldg(&g_dst[j + 3]);
        float v0 = __ldg(&g_val[j]),     v1 = __ldg(&g_val[j + 1]);
        float v2 = __ldg(&g_val[j + 2]), v3 = __ldg(&g_val[j + 3]);
        float4 a0 = fin[(size_t)d0 * 32 + lane];
        float4 a1 = fin[(size_t)d1 * 32 + lane];
        float4 a2 = fin[(size_t)d2 * 32 + lane];
        float4 a3 = fin[(size_t)d3 * 32 + lane];
        acc.x = fmaf(v0, a0.x, fmaf(v1, a1.x, fmaf(v2, a2.x, fmaf(v3, a3.x, acc.x))));
        acc.y = fmaf(v0, a0.y, fmaf(v1, a1.y, fmaf(v2, a2.y, fmaf(v3, a3.y, acc.y))));
        acc.z = fmaf(v0, a0.z, fmaf(v1, a1.z, fmaf(v2, a2.z, fmaf(v3, a3.z, acc.z))));
        acc.w = fmaf(v0, a0.w, fmaf(v1, a1.w, fmaf(v2, a2.w, fmaf(v3, a3.w, acc.w))));
    }
    for (; j < end; j++) {
        int   d = __ldg(&g_dst[j]);
        float v = __ldg(&g_val[j]);
        float4 a = fin[(size_t)d * 32 + lane];
        acc.x = fmaf(v, a.x, acc.x);
        acc.y = fmaf(v, a.y, acc.y);
        acc.z = fmaf(v, a.z, acc.z);
        acc.w = fmaf(v, a.w, acc.w);
    }
    fout[(size_t)warp * 32 + lane] = acc;
}

// ---------------- W -> bf16 hi/lo, pre-swizzled SW128 chunks ------------------
__global__ void wconv_kernel(const float* __restrict__ W) {
    int i = blockIdx.x * blockDim.x + threadIdx.x;   // over 128 * 384
    if (i >= 128 * KTOT) return;
    int n = i / KTOT, k = i % KTOT;
    float v = W[i];
    __nv_bfloat16 h = __float2bfloat16(v);
    float rh = __bfloat162float(h);
    __nv_bfloat16 l = __float2bfloat16(v - rh);
    int c = k >> 6, kk = k & 63;
    uint32_t bo = (uint32_t)n * 128 + kk * 2;
    uint32_t sw = swz(bo);
    *(__nv_bfloat16*)(g_Wh + c * 16384 + sw) = h;
    *(__nv_bfloat16*)(g_Wl + c * 16384 + sw) = l;
}

// ---------------- mma.sync GEMM: out = [x|f1|f2] @ W^T + b --------------------
// CTA: 128 rows x 128 cols, K=384 in six 64-chunks, bf16 split-2 (3 products).
// 8 warps as 4(m) x 2(n); warp tile 32x64. Fragments via ldmatrix from SW128 SMEM.
#define SMEM_GEMM_BYTES (1024 + 4 * 16384)

__global__ __launch_bounds__(256, 2)
void gemm_mma_kernel(const float* __restrict__ x,
                     const float* __restrict__ bias,
                     float* __restrict__ out) {
    extern __shared__ unsigned char dsm[];
    const int tid  = threadIdx.x;
    const int lane = tid & 31;
    const int wid  = tid >> 5;
    const int warp_m = wid & 3;       // 4 m-warps, 32 rows each
    const int warp_n = wid >> 2;      // 2 n-warps, 64 cols each
    const int rbase  = blockIdx.x * 128;

    uint32_t sb0  = smem_u32(dsm);
    uint32_t base = (sb0 + 1023) & ~1023u;
    unsigned char* gp = dsm + (base - sb0);
    const uint32_t Ah = base, Al = base + 16384, Bh = base + 32768, Bl = base + 49152;

    // ---- chunk loader: A fp32 -> bf16 hi/lo swizzled; B copied pre-swizzled --
    auto load_chunk = [&](int c) {
        const float* srcp = (c < 2) ? x : (c < 4) ? g_f1 : g_f2;
        const float4* s4 = (const float4*)srcp;
        int koff = (c & 1) * 16;
        unsigned char* pAh = gp;
        unsigned char* pAl = gp + 16384;
        #pragma unroll
        for (int it = 0; it < 8; it++) {
            int idx = tid + it * 256;                  // 2048 float4s
            int row = idx >> 4, c4 = idx & 15;
            int grow = rbase + row;
            float4 v = make_float4(0.f, 0.f, 0.f, 0.f);
            if (grow < NN) v = s4[(size_t)grow * 32 + koff + c4];
            __nv_bfloat16 h0 = __float2bfloat16(v.x), h1 = __float2bfloat16(v.y);
            __nv_bfloat16 h2 = __float2bfloat16(v.z), h3 = __float2bfloat16(v.w);
            __nv_bfloat16 l0 = __float2bfloat16(v.x - __bfloat162float(h0));
            __nv_bfloat16 l1 = __float2bfloat16(v.y - __bfloat162float(h1));
            __nv_bfloat16 l2 = __float2bfloat16(v.z - __bfloat162float(h2));
            __nv_bfloat16 l3 = __float2bfloat16(v.w - __bfloat162float(h3));
            uint32_t hw0 = (uint32_t)__bfloat16_as_ushort(h0) |
                           ((uint32_t)__bfloat16_as_ushort(h1) << 16);
            uint32_t hw1 = (uint32_t)__bfloat16_as_ushort(h2) |
                           ((uint32_t)__bfloat16_as_ushort(h3) << 16);
            uint32_t lw0 = (uint32_t)__bfloat16_as_ushort(l0) |
                           ((uint32_t)__bfloat16_as_ushort(l1) << 16);
            uint32_t lw1 = (uint32_t)__bfloat16_as_ushort(l2) |
                           ((uint32_t)__bfloat16_as_ushort(l3) << 16);
            uint32_t sw = swz((uint32_t)row * 128 + c4 * 8);
            *(uint2*)(pAh + sw) = make_uint2(hw0, hw1);
            *(uint2*)(pAl + sw) = make_uint2(lw0, lw1);
        }
        const uint4* wh = (const uint4*)(g_Wh + c * 16384);
        const uint4* wl = (const uint4*)(g_Wl + c * 16384);
        uint4* pBh = (uint4*)(gp + 32768);
        uint4* pBl = (uint4*)(gp + 49152);
        #pragma unroll
        for (int it = 0; it < 4; it++) {
            int i = tid + it * 256;
            pBh[i] = wh[i];
            pBl[i] = wl[i];
        }
    };

    float acc[2][8][4];
    #pragma unroll
    for (int mf = 0; mf < 2; mf++)
        #pragma unroll
        for (int nf = 0; nf < 8; nf++)
            #pragma unroll
            for (int q = 0; q < 4; q++) acc[mf][nf][q] = 0.f;

    // ldmatrix per-lane address components
    const int g = lane >> 3, r = lane & 7;
    const int a_row_off = r + (g & 1) * 8;     // A: g0=m,g1=m+8,g2=m k+8,g3=m+8 k+8
    const int a_k_off   = (g >> 1) * 8;
    const int b_n_off   = r + (g >> 1) * 8;    // B: g0=n,g1=n k+8,g2=n+8,g3=n+8 k+8
    const int b_k_off   = (g & 1) * 8;

    load_chunk(0);
    __syncthreads();

    for (int c = 0; c < 6; c++) {
        #pragma unroll
        for (int ks = 0; ks < 4; ks++) {
            const int k0 = ks * 16;
            uint32_t ah[2][4], al[2][4];
            #pragma unroll
            for (int mf = 0; mf < 2; mf++) {
                uint32_t bo = (uint32_t)(warp_m * 32 + mf * 16 + a_row_off) * 128
                              + (k0 + a_k_off) * 2;
                uint32_t sw = swz(bo);
                LDSM4(ah[mf], Ah + sw);
                LDSM4(al[mf], Al + sw);
            }
            #pragma unroll
            for (int bq = 0; bq < 4; bq++) {
                uint32_t bo = (uint32_t)(warp_n * 64 + bq * 16 + b_n_off) * 128
                              + (k0 + b_k_off) * 2;
                uint32_t sw = swz(bo);
                uint32_t bh[4], bl[4];
                LDSM4(bh, Bh + sw);
                LDSM4(bl, Bl + sw);
                #pragma unroll
                for (int mf = 0; mf < 2; mf++) {
                    MMA16816(acc[mf][bq * 2 + 0], ah[mf], bh[0], bh[1]);
                    MMA16816(acc[mf][bq * 2 + 0], ah[mf], bl[0], bl[1]);
                    MMA16816(acc[mf][bq * 2 + 0], al[mf], bh[0], bh[1]);
                    MMA16816(acc[mf][bq * 2 + 1], ah[mf], bh[2], bh[3]);
                    MMA16816(acc[mf][bq * 2 + 1], ah[mf], bl[2], bl[3]);
                    MMA16816(acc[mf][bq * 2 + 1], al[mf], bh[2], bh[3]);
                }
            }
        }
        if (c < 5) {
            __syncthreads();
            load_chunk(c + 1);
            __syncthreads();
        }
    }

    // ---- epilogue: bias + store ----
    const int qrow = lane >> 2, qcol = (lane & 3) * 2;
    #pragma unroll
    for (int nf = 0; nf < 8; nf++) {
        int col = warp_n * 64 + nf * 8 + qcol;
        float b0 = __ldg(&bias[col]);
        float b1 = __ldg(&bias[col + 1]);
        #pragma unroll
        for (int mf = 0; mf < 2; mf++) {
            int row0 = rbase + warp_m * 32 + mf * 16 + qrow;
            if (row0 < NN)
                *(float2*)(out + (size_t)row0 * 128 + col) =
                    make_float2(acc[mf][nf][0] + b0, acc[mf][nf][1] + b1);
            int row1 = row0 + 8;
            if (row1 < NN)
                *(float2*)(out + (size_t)row1 * 128 + col) =
                    make_float2(acc[mf][nf][2] + b0, acc[mf][nf][3] + b1);
        }
    }
}

// ---------------- launch ------------------------------------------------------
extern "C" void kernel_launch(void* const* d_in, const int* in_sizes, int n_in,
                              void* d_out, int out_size) {
    const float* x        = (const float*)d_in[0];
    const int*   edge_src = (const int*)  d_in[1];
    const int*   edge_dst = (const int*)  d_in[2];
    const float* edge_val = (const float*)d_in[3];
    const float* W        = (const float*)d_in[4];
    const float* b        = (const float*)d_in[5];
    float* out = (float*)d_out;

    static bool attr_set = false;
    if (!attr_set) {
        cudaFuncSetAttribute(gemm_mma_kernel,
                             cudaFuncAttributeMaxDynamicSharedMemorySize,
                             SMEM_GEMM_BYTES);
        attr_set = true;
    }

    float *f1p, *f2p;
    cudaGetSymbolAddress((void**)&f1p, g_f1);
    cudaGetSymbolAddress((void**)&f2p, g_f2);

    // 1) CSR build (keyed by edge_src)
    zero_deg_kernel<<<(NN + 255) / 256, 256>>>();
    hist_kernel<<<(EE + 255) / 256, 256>>>(edge_src);
    scan_kernel<<<1, 1024>>>();
    scatter_kernel<<<(EE + 255) / 256, 256>>>(edge_src, edge_dst, edge_val);

    // 2) Two SpMM hops
    int spmm_blocks = (NN + 7) / 8;
    spmm_kernel<<<spmm_blocks, 256>>>((const float4*)x,  (float4*)f1p);
    spmm_kernel<<<spmm_blocks, 256>>>((const float4*)f1p, (float4*)f2p);

    // 3) W split precompute + tensor-core dense layer
    wconv_kernel<<<(128 * KTOT + 255) / 256, 256>>>(W);
    gemm_mma_kernel<<<(NN + 127) / 128, 256, SMEM_GEMM_BYTES>>>(x, b, out);
}